// round 3
// baseline (speedup 1.0000x reference)
#include <cuda_runtime.h>
#include <cuda_bf16.h>

// Problem constants
#define BB 4
#define HH 16
#define LL 8192
#define DD 64
#define BH (BB*HH)            // 64
#define NPOS (BH*LL)          // 524288

// Kernel-1 tiling
#define TS 128                // positions per block
#define KH 64                 // k-steps per phase (q-phase, k-phase)
#define WST 68                // padded row stride for Ws (floats), mult of 4

// Scratch (no cudaMalloc allowed)
__device__ float g_w[NPOS];
__device__ float g_rsum[BH];

__device__ __forceinline__ float tanh_fast(float x) {
    float xc = fminf(fmaxf(x, -15.f), 15.f);
    float z = __expf(2.f * xc);
    return __fdividef(z - 1.f, z + 1.f);
}

#define FMA_F32X2(acc, x2, w2) \
    asm("fma.rn.f32x2 %0, %1, %2, %0;" : "+l"(acc) : "l"(x2), "l"(w2))

#define PACK_BCAST(out, f) \
    asm("mov.b64 %0, {%1, %1};" : "=l"(out) : "f"(f))

#define UNPACK2(lo, hi, in) \
    asm("mov.b64 {%0, %1}, %2;" : "=f"(lo), "=f"(hi) : "l"(in))

// ---------------------------------------------------------------------------
// Kernel 1: per-position e = va . tanh(Wa q + Ua k + b), w = mask ? exp(e) : 0
// Tile: 128 positions x 64 out-dims. 128 threads, each 8 pos x 8 dims.
// Two K-phases (q*Wa then k*Ua). Packed fma.rn.f32x2, pairs along positions.
// ---------------------------------------------------------------------------
__global__ __launch_bounds__(128, 4) void attn_logits_kernel(
    const float* __restrict__ q, const float* __restrict__ k,
    const int* __restrict__ mask,
    const float* __restrict__ Wa_w, const float* __restrict__ Wa_b,
    const float* __restrict__ Ua_w, const float* __restrict__ Ua_b,
    const float* __restrict__ va_w, const float* __restrict__ va_b)
{
    extern __shared__ float sm[];
    float* Ws   = sm;                      // [KH][WST]  weights, Ws[kk][d]
    float* Xs   = Ws + KH * WST;           // [KH][TS]   inputs,  Xs[kk][pos]
    float* bias = Xs + KH * TS;            // [64]
    float* vas  = bias + DD;               // [64]

    const int t = threadIdx.x;             // 0..127
    const int pos0 = blockIdx.x * TS;      // global flat position base

    if (t < 64) {
        bias[t] = Wa_b[t] + Ua_b[t];
        vas[t]  = va_w[t];
    }

    const int tx = t & 7;    // dim group: dims 8*tx .. 8*tx+7
    const int ty = t >> 3;   // pos group: pos  8*ty .. 8*ty+7

    // acc2[pp][d]: packed (pos 2*pp, pos 2*pp+1) for dim 8*tx+d
    unsigned long long acc2[4][8];
    #pragma unroll
    for (int i = 0; i < 4; i++)
        #pragma unroll
        for (int j = 0; j < 8; j++) acc2[i][j] = 0ull;

    const int d_ld  = t & 63;              // weight-load: output dim
    const int sub   = t >> 6;              // half selector (0/1)

    #pragma unroll 1
    for (int ph = 0; ph < 2; ph++) {
        const float* W = ph ? Ua_w : Wa_w;
        const float* X = ph ? k : q;

        if (ph) __syncthreads();           // prior compute done before overwrite

        // weights transposed: Ws[kk][d] = W[d][kk], kk in [32*sub, 32*sub+32)
        {
            const float4* w4 = (const float4*)(W + d_ld * DD + 32 * sub);
            #pragma unroll
            for (int i = 0; i < 8; i++) {
                float4 a = w4[i];
                int kk = 32 * sub + 4 * i;
                Ws[(kk + 0) * WST + d_ld] = a.x;
                Ws[(kk + 1) * WST + d_ld] = a.y;
                Ws[(kk + 2) * WST + d_ld] = a.z;
                Ws[(kk + 3) * WST + d_ld] = a.w;
            }
        }
        // x transposed: Xs[kk][p] = X[pos0+p][kk], p = t (128 positions)
        {
            const float4* x4 = (const float4*)(X + (size_t)(pos0 + t) * DD);
            #pragma unroll
            for (int i = 0; i < 16; i++) {
                float4 a = x4[i];
                int kk = 4 * i;
                Xs[(kk + 0) * TS + t] = a.x;
                Xs[(kk + 1) * TS + t] = a.y;
                Xs[(kk + 2) * TS + t] = a.z;
                Xs[(kk + 3) * TS + t] = a.w;
            }
        }
        __syncthreads();

        #pragma unroll 4
        for (int kk = 0; kk < KH; kk++) {
            float4 wlo = *(const float4*)&Ws[kk * WST + 8 * tx];
            float4 whi = *(const float4*)&Ws[kk * WST + 8 * tx + 4];
            ulonglong2 xa = *(const ulonglong2*)&Xs[kk * TS + 8 * ty];
            ulonglong2 xb = *(const ulonglong2*)&Xs[kk * TS + 8 * ty + 4];
            unsigned long long xp[4] = {xa.x, xa.y, xb.x, xb.y};
            unsigned long long w2[8];
            PACK_BCAST(w2[0], wlo.x);
            PACK_BCAST(w2[1], wlo.y);
            PACK_BCAST(w2[2], wlo.z);
            PACK_BCAST(w2[3], wlo.w);
            PACK_BCAST(w2[4], whi.x);
            PACK_BCAST(w2[5], whi.y);
            PACK_BCAST(w2[6], whi.z);
            PACK_BCAST(w2[7], whi.w);
            #pragma unroll
            for (int pp = 0; pp < 4; pp++) {
                #pragma unroll
                for (int d = 0; d < 8; d++)
                    FMA_F32X2(acc2[pp][d], xp[pp], w2[d]);
            }
        }
    }

    // ---- epilogue: tanh, va-dot over 8 dims, 8-lane reduce, masked exp ----
    float bs[8], vs[8];
    #pragma unroll
    for (int d = 0; d < 8; d++) {
        bs[d] = bias[8 * tx + d];
        vs[d] = vas[8 * tx + d];
    }
    float vb = va_b[0];

    float ep[8];
    #pragma unroll
    for (int pp = 0; pp < 4; pp++) {
        float s0 = 0.f, s1 = 0.f;
        #pragma unroll
        for (int d = 0; d < 8; d++) {
            float a0, a1;
            UNPACK2(a0, a1, acc2[pp][d]);
            s0 += vs[d] * tanh_fast(a0 + bs[d]);
            s1 += vs[d] * tanh_fast(a1 + bs[d]);
        }
        #pragma unroll
        for (int m = 4; m >= 1; m >>= 1) {
            s0 += __shfl_xor_sync(0xffffffffu, s0, m, 8);
            s1 += __shfl_xor_sync(0xffffffffu, s1, m, 8);
        }
        ep[2 * pp] = s0;
        ep[2 * pp + 1] = s1;
    }

    if (tx == 0) {
        #pragma unroll
        for (int i = 0; i < 8; i++) {
            int pos = pos0 + 8 * ty + i;
            float e = ep[i] + vb;
            float w = (mask[pos] != 0) ? __expf(e) : 0.f;
            g_w[pos] = w;
        }
    }
}

// ---------------------------------------------------------------------------
// Kernel 2: per-(b,h) sum of w over L, store reciprocal. Deterministic.
// ---------------------------------------------------------------------------
__global__ __launch_bounds__(256) void row_sum_kernel()
{
    __shared__ float red[256];
    int bh = blockIdx.x;
    int t = threadIdx.x;
    float s = 0.f;
    const float4* wrow = (const float4*)(g_w + (size_t)bh * LL);
    for (int l = t; l < LL / 4; l += 256) {
        float4 w4 = wrow[l];
        s += (w4.x + w4.y) + (w4.z + w4.w);
    }
    red[t] = s;
    __syncthreads();
    for (int m = 128; m > 0; m >>= 1) {
        if (t < m) red[t] += red[t + m];
        __syncthreads();
    }
    if (t == 0) g_rsum[bh] = 1.f / red[0];
}

// ---------------------------------------------------------------------------
// Kernel 3: out = alpha * v  (float4)
// ---------------------------------------------------------------------------
__global__ __launch_bounds__(1024) void scale_v_kernel(
    const float* __restrict__ v, float* __restrict__ out)
{
    int i4 = blockIdx.x * 1024 + threadIdx.x;   // 8192 blocks * 1024 = N/4 exactly
    int pos = i4 >> 4;                           // 16 float4 per position
    int bh  = pos >> 13;                         // / 8192
    float w = g_w[pos] * g_rsum[bh];
    float4 vv = ((const float4*)v)[i4];
    vv.x *= w; vv.y *= w; vv.z *= w; vv.w *= w;
    ((float4*)out)[i4] = vv;
}

extern "C" void kernel_launch(void* const* d_in, const int* in_sizes, int n_in,
                              void* d_out, int out_size)
{
    const float* q    = (const float*)d_in[0];
    const float* k    = (const float*)d_in[1];
    const float* v    = (const float*)d_in[2];
    const int*   mask = (const int*)d_in[3];
    const float* Wa_w = (const float*)d_in[4];
    const float* Wa_b = (const float*)d_in[5];
    const float* Ua_w = (const float*)d_in[6];
    const float* Ua_b = (const float*)d_in[7];
    const float* va_w = (const float*)d_in[8];
    const float* va_b = (const float*)d_in[9];
    float* out = (float*)d_out;

    const int smem1 = (KH * WST + KH * TS + 2 * DD) * (int)sizeof(float); // 50688 B
    cudaFuncSetAttribute(attn_logits_kernel,
                         cudaFuncAttributeMaxDynamicSharedMemorySize, smem1);

    attn_logits_kernel<<<NPOS / TS, 128, smem1>>>(q, k, mask, Wa_w, Wa_b,
                                                  Ua_w, Ua_b, va_w, va_b);
    row_sum_kernel<<<BH, 256>>>();
    scale_v_kernel<<<(NPOS * DD / 4) / 1024, 1024>>>(v, out);
}

// round 5
// speedup vs baseline: 2.0700x; 2.0700x over previous
#include <cuda_runtime.h>
#include <cuda_bf16.h>
#include <cstdint>

// Problem constants
#define BB 4
#define HH 16
#define LL 8192
#define DD 64
#define BH (BB*HH)            // 64
#define NPOS (BH*LL)          // 524288

#define TS 128                // positions per block (M tile)
#define P  68                 // padded row stride (floats); 68 mod 32 == 4
#define NWARP 4

// Scratch (no cudaMalloc allowed)
__device__ float g_w[NPOS];
__device__ float g_rsum[BH];

__device__ __forceinline__ float tanh_fast(float x) {
    float xc = fminf(fmaxf(x, -15.f), 15.f);
    float z = __expf(2.f * xc);
    return __fdividef(z - 1.f, z + 1.f);
}

__device__ __forceinline__ float f2tf32(float f) {
    uint32_t r;
    asm("cvt.rna.tf32.f32 %0, %1;" : "=r"(r) : "f"(f));
    return __uint_as_float(r);
}

#define MMA_TF32(c, a, b0_, b1_) \
    asm volatile( \
        "mma.sync.aligned.m16n8k8.row.col.f32.tf32.tf32.f32 " \
        "{%0,%1,%2,%3}, {%4,%5,%6,%7}, {%8,%9}, {%0,%1,%2,%3};" \
        : "+f"((c)[0]), "+f"((c)[1]), "+f"((c)[2]), "+f"((c)[3]) \
        : "r"((a)[0]), "r"((a)[1]), "r"((a)[2]), "r"((a)[3]), \
          "r"(b0_), "r"(b1_))

// ---------------------------------------------------------------------------
// Kernel 1: tf32 mma.sync GEMM [128pos x 64dims, K=128 in 2 phases] + epilogue
//   e = va . tanh(Wa q + Ua k + b);  w = mask ? exp(e) : 0
// ---------------------------------------------------------------------------
__global__ __launch_bounds__(128) void attn_logits_kernel(
    const float* __restrict__ q, const float* __restrict__ k,
    const int* __restrict__ mask,
    const float* __restrict__ Wa_w, const float* __restrict__ Wa_b,
    const float* __restrict__ Ua_w, const float* __restrict__ Ua_b,
    const float* __restrict__ va_w, const float* __restrict__ va_b)
{
    extern __shared__ float sm[];
    float* Xs   = sm;                 // [128][P]
    float* Ws   = Xs + TS * P;        // [64][P]
    float* bias = Ws + DD * P;        // [64]
    float* vas  = bias + DD;          // [64]

    const int t    = threadIdx.x;
    const int lane = t & 31;
    const int w    = t >> 5;
    const int gid  = lane >> 2;       // 0..7
    const int tig  = lane & 3;        // 0..3
    const int pos0 = blockIdx.x * TS;
    const int m0   = w * 32;          // warp's row base within tile

    float acc[2][8][4];
    #pragma unroll
    for (int mt = 0; mt < 2; mt++)
        #pragma unroll
        for (int nt = 0; nt < 8; nt++)
            #pragma unroll
            for (int j = 0; j < 4; j++) acc[mt][nt][j] = 0.f;

    if (t < 64) {
        bias[t] = Wa_b[t] + Ua_b[t];
        vas[t]  = va_w[t];
    }

    const int n_st = t & 63;          // weight stage row
    const int hf   = t >> 6;          // weight stage col half

    #pragma unroll 1
    for (int ph = 0; ph < 2; ph++) {
        const float* X = ph ? k : q;
        const float* W = ph ? Ua_w : Wa_w;

        if (ph) __syncthreads();

        // stage X: row t (position), 64 cols, cvt to tf32 bits
        {
            const float4* x4 = (const float4*)(X + (size_t)(pos0 + t) * DD);
            float* dst = Xs + t * P;
            #pragma unroll
            for (int i = 0; i < 16; i++) {
                float4 a = x4[i];
                a.x = f2tf32(a.x); a.y = f2tf32(a.y);
                a.z = f2tf32(a.z); a.w = f2tf32(a.w);
                *(float4*)(dst + 4 * i) = a;
            }
        }
        // stage W: row n_st, cols 32*hf..32*hf+31
        {
            const float4* w4 = (const float4*)(W + n_st * DD + 32 * hf);
            float* dst = Ws + n_st * P + 32 * hf;
            #pragma unroll
            for (int i = 0; i < 8; i++) {
                float4 a = w4[i];
                a.x = f2tf32(a.x); a.y = f2tf32(a.y);
                a.z = f2tf32(a.z); a.w = f2tf32(a.w);
                *(float4*)(dst + 4 * i) = a;
            }
        }
        __syncthreads();

        #pragma unroll
        for (int ks = 0; ks < 8; ks++) {
            const int k0 = ks * 8;
            // B fragments: n-tile nt covers cols nt*8..nt*8+7
            uint32_t b0[8], b1[8];
            const float* wb = Ws + gid * P + k0 + tig;
            #pragma unroll
            for (int nt = 0; nt < 8; nt++) {
                b0[nt] = __float_as_uint(wb[nt * 8 * P]);
                b1[nt] = __float_as_uint(wb[nt * 8 * P + 4]);
            }
            // A fragments: m-tile mt covers rows m0+mt*16 .. +15
            uint32_t a[2][4];
            const float* ab = Xs + (m0 + gid) * P + k0 + tig;
            #pragma unroll
            for (int mt = 0; mt < 2; mt++) {
                const float* ar = ab + mt * 16 * P;
                a[mt][0] = __float_as_uint(ar[0]);
                a[mt][1] = __float_as_uint(ar[8 * P]);
                a[mt][2] = __float_as_uint(ar[4]);
                a[mt][3] = __float_as_uint(ar[8 * P + 4]);
            }
            #pragma unroll
            for (int mt = 0; mt < 2; mt++)
                #pragma unroll
                for (int nt = 0; nt < 8; nt++)
                    MMA_TF32(acc[mt][nt], a[mt], b0[nt], b1[nt]);
        }
    }

    // ---- epilogue ----
    const float vb = va_b[0];
    #pragma unroll
    for (int mt = 0; mt < 2; mt++) {
        float s0 = 0.f, s1 = 0.f;
        #pragma unroll
        for (int nt = 0; nt < 8; nt++) {
            const int c0 = nt * 8 + 2 * tig;
            const float vv0 = vas[c0], vv1 = vas[c0 + 1];
            const float bb0 = bias[c0], bb1 = bias[c0 + 1];
            s0 += vv0 * tanh_fast(acc[mt][nt][0] + bb0)
                + vv1 * tanh_fast(acc[mt][nt][1] + bb1);
            s1 += vv0 * tanh_fast(acc[mt][nt][2] + bb0)
                + vv1 * tanh_fast(acc[mt][nt][3] + bb1);
        }
        s0 += __shfl_xor_sync(0xffffffffu, s0, 1, 4);
        s0 += __shfl_xor_sync(0xffffffffu, s0, 2, 4);
        s1 += __shfl_xor_sync(0xffffffffu, s1, 1, 4);
        s1 += __shfl_xor_sync(0xffffffffu, s1, 2, 4);
        if (tig == 0) {
            int p0 = pos0 + m0 + mt * 16 + gid;
            float e0 = s0 + vb;
            g_w[p0] = (mask[p0] != 0) ? __expf(e0) : 0.f;
            int p1 = p0 + 8;
            float e1 = s1 + vb;
            g_w[p1] = (mask[p1] != 0) ? __expf(e1) : 0.f;
        }
    }
}

// ---------------------------------------------------------------------------
// Kernel 2: per-(b,h) sum of w over L, store reciprocal. Deterministic.
// ---------------------------------------------------------------------------
__global__ __launch_bounds__(256) void row_sum_kernel()
{
    __shared__ float red[256];
    int bh = blockIdx.x;
    int t = threadIdx.x;
    float s = 0.f;
    const float4* wrow = (const float4*)(g_w + (size_t)bh * LL);
    for (int l = t; l < LL / 4; l += 256) {
        float4 w4 = wrow[l];
        s += (w4.x + w4.y) + (w4.z + w4.w);
    }
    red[t] = s;
    __syncthreads();
    for (int m = 128; m > 0; m >>= 1) {
        if (t < m) red[t] += red[t + m];
        __syncthreads();
    }
    if (t == 0) g_rsum[bh] = 1.f / red[0];
}

// ---------------------------------------------------------------------------
// Kernel 3: out = alpha * v  (float4)
// ---------------------------------------------------------------------------
__global__ __launch_bounds__(1024) void scale_v_kernel(
    const float* __restrict__ v, float* __restrict__ out)
{
    int i4 = blockIdx.x * 1024 + threadIdx.x;   // 8192 blocks * 1024 = N/4 exactly
    int pos = i4 >> 4;                           // 16 float4 per position
    int bh  = pos >> 13;                         // / 8192
    float w = g_w[pos] * g_rsum[bh];
    float4 vv = ((const float4*)v)[i4];
    vv.x *= w; vv.y *= w; vv.z *= w; vv.w *= w;
    ((float4*)out)[i4] = vv;
}

extern "C" void kernel_launch(void* const* d_in, const int* in_sizes, int n_in,
                              void* d_out, int out_size)
{
    const float* q    = (const float*)d_in[0];
    const float* k    = (const float*)d_in[1];
    const float* v    = (const float*)d_in[2];
    const int*   mask = (const int*)d_in[3];
    const float* Wa_w = (const float*)d_in[4];
    const float* Wa_b = (const float*)d_in[5];
    const float* Ua_w = (const float*)d_in[6];
    const float* Ua_b = (const float*)d_in[7];
    const float* va_w = (const float*)d_in[8];
    const float* va_b = (const float*)d_in[9];
    float* out = (float*)d_out;

    const int smem1 = (TS * P + DD * P + 2 * DD) * (int)sizeof(float); // 52736 B
    cudaFuncSetAttribute(attn_logits_kernel,
                         cudaFuncAttributeMaxDynamicSharedMemorySize, smem1);

    attn_logits_kernel<<<NPOS / TS, 128, smem1>>>(q, k, mask, Wa_w, Wa_b,
                                                  Ua_w, Ua_b, va_w, va_b);
    row_sum_kernel<<<BH, 256>>>();
    scale_v_kernel<<<(NPOS * DD / 4) / 1024, 1024>>>(v, out);
}

// round 6
// speedup vs baseline: 2.4821x; 1.1990x over previous
#include <cuda_runtime.h>
#include <cuda_bf16.h>
#include <cstdint>

// Problem constants
#define BB 4
#define HH 16
#define LL 8192
#define DD 64
#define BH (BB*HH)            // 64
#define NPOS (BH*LL)          // 524288

#define TS 128                // positions per block (M tile)
#define RS 72                 // bf16 row stride (elements); 144 bytes
#define RSB 144               // row stride bytes

// Scratch (no cudaMalloc allowed)
__device__ float g_w[NPOS];
__device__ float g_rsum[BH];

__device__ __forceinline__ float tanh_fast(float x) {
    float xc = fminf(fmaxf(x, -15.f), 15.f);
    float z = __expf(2.f * xc);
    return __fdividef(z - 1.f, z + 1.f);
}

__device__ __forceinline__ uint32_t pack_bf16(float lo, float hi) {
    uint32_t r;
    asm("cvt.rn.bf16x2.f32 %0, %1, %2;" : "=r"(r) : "f"(hi), "f"(lo));
    return r;
}

#define LDSM_X4(r, addr) \
    asm volatile("ldmatrix.sync.aligned.m8n8.x4.shared.b16 {%0,%1,%2,%3}, [%4];" \
        : "=r"((r)[0]), "=r"((r)[1]), "=r"((r)[2]), "=r"((r)[3]) : "r"(addr))

#define MMA_BF16(c, a, b0_, b1_) \
    asm volatile( \
        "mma.sync.aligned.m16n8k16.row.col.f32.bf16.bf16.f32 " \
        "{%0,%1,%2,%3}, {%4,%5,%6,%7}, {%8,%9}, {%0,%1,%2,%3};" \
        : "+f"((c)[0]), "+f"((c)[1]), "+f"((c)[2]), "+f"((c)[3]) \
        : "r"((a)[0]), "r"((a)[1]), "r"((a)[2]), "r"((a)[3]), \
          "r"(b0_), "r"(b1_))

// ---------------------------------------------------------------------------
// Kernel 1: bf16 mma.sync GEMM [128pos x 64dims, K=128 in 2 phases] + epilogue
//   e = va . tanh(Wa q + Ua k + b);  w = mask ? exp(e) : 0
// ---------------------------------------------------------------------------
__global__ __launch_bounds__(128) void attn_logits_kernel(
    const float* __restrict__ q, const float* __restrict__ k,
    const int* __restrict__ mask,
    const float* __restrict__ Wa_w, const float* __restrict__ Wa_b,
    const float* __restrict__ Ua_w, const float* __restrict__ Ua_b,
    const float* __restrict__ va_w, const float* __restrict__ va_b)
{
    __shared__ alignas(16) __nv_bfloat16 Xs[TS * RS];   // [128 pos][64 k] +pad
    __shared__ alignas(16) __nv_bfloat16 Wsm[DD * RS];  // [64 n][64 k] +pad
    __shared__ float bias[DD];
    __shared__ float vas[DD];

    const int t    = threadIdx.x;
    const int lane = t & 31;
    const int w    = t >> 5;
    const int gid  = lane >> 2;       // 0..7
    const int tig  = lane & 3;        // 0..3
    const int pos0 = blockIdx.x * TS;
    const int m0   = w * 32;          // warp's row base within tile

    const uint32_t sbX = (uint32_t)__cvta_generic_to_shared(Xs);
    const uint32_t sbW = (uint32_t)__cvta_generic_to_shared(Wsm);

    float acc[2][8][4];
    #pragma unroll
    for (int mt = 0; mt < 2; mt++)
        #pragma unroll
        for (int nt = 0; nt < 8; nt++)
            #pragma unroll
            for (int j = 0; j < 4; j++) acc[mt][nt][j] = 0.f;

    if (t < 64) {
        bias[t] = Wa_b[t] + Ua_b[t];
        vas[t]  = va_w[t];
    }

    // ldmatrix lane addressing (constant across phases/ksteps up to offsets)
    const uint32_t aAddr = sbX + (uint32_t)(m0 + (lane & 15)) * RSB
                               + (uint32_t)((lane >> 4) << 3) * 2u;
    const int nB = ((lane >> 4) << 3) + (lane & 7);
    const int kB = ((lane >> 3) & 1) << 3;
    const uint32_t bAddr = sbW + (uint32_t)nB * RSB + (uint32_t)kB * 2u;

    #pragma unroll 1
    for (int ph = 0; ph < 2; ph++) {
        const float* X = ph ? k : q;
        const float* W = ph ? Ua_w : Wa_w;

        if (ph) __syncthreads();

        // stage X row t: 64 fp32 -> 64 bf16 (128 B)
        {
            const float4* x4 = (const float4*)(X + (size_t)(pos0 + t) * DD);
            uint4* dst = (uint4*)((char*)Xs + t * RSB);
            #pragma unroll
            for (int i = 0; i < 8; i++) {
                float4 a = x4[2 * i], b = x4[2 * i + 1];
                uint4 u;
                u.x = pack_bf16(a.x, a.y);
                u.y = pack_bf16(a.z, a.w);
                u.z = pack_bf16(b.x, b.y);
                u.w = pack_bf16(b.z, b.w);
                dst[i] = u;
            }
        }
        // stage W row t (t < 64)
        if (t < DD) {
            const float4* w4 = (const float4*)(W + t * DD);
            uint4* dst = (uint4*)((char*)Wsm + t * RSB);
            #pragma unroll
            for (int i = 0; i < 8; i++) {
                float4 a = w4[2 * i], b = w4[2 * i + 1];
                uint4 u;
                u.x = pack_bf16(a.x, a.y);
                u.y = pack_bf16(a.z, a.w);
                u.z = pack_bf16(b.x, b.y);
                u.w = pack_bf16(b.z, b.w);
                dst[i] = u;
            }
        }
        __syncthreads();

        #pragma unroll
        for (int ks = 0; ks < 4; ks++) {      // K=64 per phase, k16 per MMA
            const uint32_t koff = (uint32_t)ks * 32u;   // 16 bf16 = 32 B
            uint32_t af[2][4];
            LDSM_X4(af[0], aAddr + koff);
            LDSM_X4(af[1], aAddr + 16u * RSB + koff);
            uint32_t bf[4][4];
            #pragma unroll
            for (int np = 0; np < 4; np++)
                LDSM_X4(bf[np], bAddr + (uint32_t)np * 16u * RSB + koff);
            #pragma unroll
            for (int mt = 0; mt < 2; mt++)
                #pragma unroll
                for (int np = 0; np < 4; np++) {
                    MMA_BF16(acc[mt][2 * np],     af[mt], bf[np][0], bf[np][1]);
                    MMA_BF16(acc[mt][2 * np + 1], af[mt], bf[np][2], bf[np][3]);
                }
        }
    }

    // ---- epilogue ----
    const float vb = va_b[0];
    #pragma unroll
    for (int mt = 0; mt < 2; mt++) {
        float s0 = 0.f, s1 = 0.f;
        #pragma unroll
        for (int nt = 0; nt < 8; nt++) {
            const int c0 = nt * 8 + 2 * tig;
            const float vv0 = vas[c0], vv1 = vas[c0 + 1];
            const float bb0 = bias[c0], bb1 = bias[c0 + 1];
            s0 += vv0 * tanh_fast(acc[mt][nt][0] + bb0)
                + vv1 * tanh_fast(acc[mt][nt][1] + bb1);
            s1 += vv0 * tanh_fast(acc[mt][nt][2] + bb0)
                + vv1 * tanh_fast(acc[mt][nt][3] + bb1);
        }
        s0 += __shfl_xor_sync(0xffffffffu, s0, 1, 4);
        s0 += __shfl_xor_sync(0xffffffffu, s0, 2, 4);
        s1 += __shfl_xor_sync(0xffffffffu, s1, 1, 4);
        s1 += __shfl_xor_sync(0xffffffffu, s1, 2, 4);
        if (tig == 0) {
            int p0 = pos0 + m0 + mt * 16 + gid;
            float e0 = s0 + vb;
            g_w[p0] = (mask[p0] != 0) ? __expf(e0) : 0.f;
            int p1 = p0 + 8;
            float e1 = s1 + vb;
            g_w[p1] = (mask[p1] != 0) ? __expf(e1) : 0.f;
        }
    }
}

// ---------------------------------------------------------------------------
// Kernel 2: per-(b,h) sum of w over L, store reciprocal. Deterministic.
// ---------------------------------------------------------------------------
__global__ __launch_bounds__(256) void row_sum_kernel()
{
    __shared__ float red[256];
    int bh = blockIdx.x;
    int t = threadIdx.x;
    float s = 0.f;
    const float4* wrow = (const float4*)(g_w + (size_t)bh * LL);
    for (int l = t; l < LL / 4; l += 256) {
        float4 w4 = wrow[l];
        s += (w4.x + w4.y) + (w4.z + w4.w);
    }
    red[t] = s;
    __syncthreads();
    for (int m = 128; m > 0; m >>= 1) {
        if (t < m) red[t] += red[t + m];
        __syncthreads();
    }
    if (t == 0) g_rsum[bh] = 1.f / red[0];
}

// ---------------------------------------------------------------------------
// Kernel 3: out = alpha * v  (float4)
// ---------------------------------------------------------------------------
__global__ __launch_bounds__(1024) void scale_v_kernel(
    const float* __restrict__ v, float* __restrict__ out)
{
    int i4 = blockIdx.x * 1024 + threadIdx.x;   // 8192 blocks * 1024 = N/4 exactly
    int pos = i4 >> 4;                           // 16 float4 per position
    int bh  = pos >> 13;                         // / 8192
    float w = g_w[pos] * g_rsum[bh];
    float4 vv = ((const float4*)v)[i4];
    vv.x *= w; vv.y *= w; vv.z *= w; vv.w *= w;
    ((float4*)out)[i4] = vv;
}

extern "C" void kernel_launch(void* const* d_in, const int* in_sizes, int n_in,
                              void* d_out, int out_size)
{
    const float* q    = (const float*)d_in[0];
    const float* k    = (const float*)d_in[1];
    const float* v    = (const float*)d_in[2];
    const int*   mask = (const int*)d_in[3];
    const float* Wa_w = (const float*)d_in[4];
    const float* Wa_b = (const float*)d_in[5];
    const float* Ua_w = (const float*)d_in[6];
    const float* Ua_b = (const float*)d_in[7];
    const float* va_w = (const float*)d_in[8];
    const float* va_b = (const float*)d_in[9];
    float* out = (float*)d_out;

    attn_logits_kernel<<<NPOS / TS, 128>>>(q, k, mask, Wa_w, Wa_b,
                                           Ua_w, Ua_b, va_w, va_b);
    row_sum_kernel<<<BH, 256>>>();
    scale_v_kernel<<<(NPOS * DD / 4) / 1024, 1024>>>(v, out);
}

// round 9
// speedup vs baseline: 2.5853x; 1.0416x over previous
#include <cuda_runtime.h>
#include <cuda_bf16.h>
#include <cstdint>

// Problem constants
#define BB 4
#define HH 16
#define LL 8192
#define DD 64
#define BH (BB*HH)            // 64
#define NPOS (BH*LL)          // 524288

#define TS 128                // positions per block (M tile)
#define KD 128                // full K (q:64 | k:64)
#define RS 136                // bf16 row stride elements (272 B; 272 mod 128 = 16)
#define RSB 272

// Scratch (no cudaMalloc allowed)
__device__ float g_w[NPOS];
__device__ float g_rsum[BH];

__device__ __forceinline__ float tanh_fast(float x) {
    float xc = fminf(fmaxf(x, -15.f), 15.f);
    float z = __expf(2.f * xc);
    return __fdividef(z - 1.f, z + 1.f);
}

__device__ __forceinline__ uint32_t pack_bf16(float lo, float hi) {
    uint32_t r;
    asm("cvt.rn.bf16x2.f32 %0, %1, %2;" : "=r"(r) : "f"(hi), "f"(lo));
    return r;
}

#define LDSM_X4(r, addr) \
    asm volatile("ldmatrix.sync.aligned.m8n8.x4.shared.b16 {%0,%1,%2,%3}, [%4];" \
        : "=r"((r)[0]), "=r"((r)[1]), "=r"((r)[2]), "=r"((r)[3]) : "r"(addr))

#define MMA_BF16(c, a, b0_, b1_) \
    asm volatile( \
        "mma.sync.aligned.m16n8k16.row.col.f32.bf16.bf16.f32 " \
        "{%0,%1,%2,%3}, {%4,%5,%6,%7}, {%8,%9}, {%0,%1,%2,%3};" \
        : "+f"((c)[0]), "+f"((c)[1]), "+f"((c)[2]), "+f"((c)[3]) \
        : "r"((a)[0]), "r"((a)[1]), "r"((a)[2]), "r"((a)[3]), \
          "r"(b0_), "r"(b1_))

// ---------------------------------------------------------------------------
// Kernel 1: bf16 mma.sync GEMM [128 pos x 64 dims, K=128 single phase]
//   e = va . tanh(Wa q + Ua k + b);  w = mask ? exp(e) : 0
// 256 threads / 8 warps; warp-tile 16 pos x 64 dims (acc = 32 regs).
// ---------------------------------------------------------------------------
__global__ __launch_bounds__(256, 3) void attn_logits_kernel(
    const float* __restrict__ q, const float* __restrict__ k,
    const int* __restrict__ mask,
    const float* __restrict__ Wa_w, const float* __restrict__ Wa_b,
    const float* __restrict__ Ua_w, const float* __restrict__ Ua_b,
    const float* __restrict__ va_w, const float* __restrict__ va_b)
{
    __shared__ alignas(16) __nv_bfloat16 Xs[TS * RS];   // [128 pos][128 k]+pad
    __shared__ alignas(16) __nv_bfloat16 Wsm[DD * RS];  // [64 n][128 k]+pad
    __shared__ float bias[DD];
    __shared__ float vas[DD];

    const int t    = threadIdx.x;      // 0..255
    const int lane = t & 31;
    const int w    = t >> 5;           // 0..7
    const int gid  = lane >> 2;        // 0..7
    const int tig  = lane & 3;         // 0..3
    const int pos0 = blockIdx.x * TS;
    const int m0   = w * 16;           // warp's 16-pos row base

    const uint32_t sbX = (uint32_t)__cvta_generic_to_shared(Xs);
    const uint32_t sbW = (uint32_t)__cvta_generic_to_shared(Wsm);

    if (t < 64) {
        bias[t] = Wa_b[t] + Ua_b[t];
        vas[t]  = va_w[t];
    }

    // ---- stage X: thread t -> row t>>1, half t&1 (q half or k half) ----
    {
        const int row  = t >> 1;
        const int half = t & 1;
        const float* src = half ? (k + (size_t)(pos0 + row) * DD)
                                : (q + (size_t)(pos0 + row) * DD);
        const float4* x4 = (const float4*)src;
        uint4* dst = (uint4*)((char*)Xs + row * RSB + half * 128);
        #pragma unroll
        for (int i = 0; i < 8; i++) {
            float4 a = x4[2 * i], b = x4[2 * i + 1];
            uint4 u;
            u.x = pack_bf16(a.x, a.y);
            u.y = pack_bf16(a.z, a.w);
            u.z = pack_bf16(b.x, b.y);
            u.w = pack_bf16(b.z, b.w);
            dst[i] = u;
        }
    }
    // ---- stage W: thread t -> row t>>2, quarter t&3 (Wa:0-1, Ua:2-3) ----
    {
        const int row = t >> 2;
        const int qt  = t & 3;
        const float* src = (qt & 2) ? (Ua_w + row * DD + (qt & 1) * 32)
                                    : (Wa_w + row * DD + (qt & 1) * 32);
        const float4* w4 = (const float4*)src;
        uint4* dst = (uint4*)((char*)Wsm + row * RSB + (qt & 2) * 64 + (qt & 1) * 64);
        #pragma unroll
        for (int i = 0; i < 4; i++) {
            float4 a = w4[2 * i], b = w4[2 * i + 1];
            uint4 u;
            u.x = pack_bf16(a.x, a.y);
            u.y = pack_bf16(a.z, a.w);
            u.z = pack_bf16(b.x, b.y);
            u.w = pack_bf16(b.z, b.w);
            dst[i] = u;
        }
    }
    __syncthreads();

    float acc[8][4];
    #pragma unroll
    for (int nt = 0; nt < 8; nt++)
        #pragma unroll
        for (int j = 0; j < 4; j++) acc[nt][j] = 0.f;

    // ldmatrix lane addressing
    const uint32_t aAddr = sbX + (uint32_t)(m0 + (lane & 15)) * RSB
                               + (uint32_t)((lane >> 4) << 3) * 2u;
    const int nB = ((lane >> 4) << 3) + (lane & 7);
    const int kB = ((lane >> 3) & 1) << 3;
    const uint32_t bAddr = sbW + (uint32_t)nB * RSB + (uint32_t)kB * 2u;

    #pragma unroll
    for (int ks = 0; ks < 8; ks++) {          // K=128, k16 per MMA
        const uint32_t koff = (uint32_t)ks * 32u;
        uint32_t af[4];
        LDSM_X4(af, aAddr + koff);
        uint32_t bf[4][4];
        #pragma unroll
        for (int np = 0; np < 4; np++)
            LDSM_X4(bf[np], bAddr + (uint32_t)np * 16u * RSB + koff);
        #pragma unroll
        for (int np = 0; np < 4; np++) {
            MMA_BF16(acc[2 * np],     af, bf[np][0], bf[np][1]);
            MMA_BF16(acc[2 * np + 1], af, bf[np][2], bf[np][3]);
        }
    }

    // ---- epilogue: tanh, va-dot, 4-lane reduce, masked exp ----
    const float vb = va_b[0];
    float s0 = 0.f, s1 = 0.f;
    #pragma unroll
    for (int nt = 0; nt < 8; nt++) {
        const int c0 = nt * 8 + 2 * tig;
        const float vv0 = vas[c0], vv1 = vas[c0 + 1];
        const float bb0 = bias[c0], bb1 = bias[c0 + 1];
        s0 += vv0 * tanh_fast(acc[nt][0] + bb0)
            + vv1 * tanh_fast(acc[nt][1] + bb1);
        s1 += vv0 * tanh_fast(acc[nt][2] + bb0)
            + vv1 * tanh_fast(acc[nt][3] + bb1);
    }
    s0 += __shfl_xor_sync(0xffffffffu, s0, 1, 4);
    s0 += __shfl_xor_sync(0xffffffffu, s0, 2, 4);
    s1 += __shfl_xor_sync(0xffffffffu, s1, 1, 4);
    s1 += __shfl_xor_sync(0xffffffffu, s1, 2, 4);
    if (tig == 0) {
        int p0 = pos0 + m0 + gid;
        float e0 = s0 + vb;
        g_w[p0] = (mask[p0] != 0) ? __expf(e0) : 0.f;
        int p1 = p0 + 8;
        float e1 = s1 + vb;
        g_w[p1] = (mask[p1] != 0) ? __expf(e1) : 0.f;
    }
}

// ---------------------------------------------------------------------------
// Kernel 2: per-(b,h) sum of w over L, store reciprocal. Deterministic.
// ---------------------------------------------------------------------------
__global__ __launch_bounds__(256) void row_sum_kernel()
{
    __shared__ float red[256];
    int bh = blockIdx.x;
    int t = threadIdx.x;
    float s = 0.f;
    const float4* wrow = (const float4*)(g_w + (size_t)bh * LL);
    for (int l = t; l < LL / 4; l += 256) {
        float4 w4 = wrow[l];
        s += (w4.x + w4.y) + (w4.z + w4.w);
    }
    red[t] = s;
    __syncthreads();
    for (int m = 128; m > 0; m >>= 1) {
        if (t < m) red[t] += red[t + m];
        __syncthreads();
    }
    if (t == 0) g_rsum[bh] = 1.f / red[0];
}

// ---------------------------------------------------------------------------
// Kernel 3: out = alpha * v  (float4)
// ---------------------------------------------------------------------------
__global__ __launch_bounds__(1024) void scale_v_kernel(
    const float* __restrict__ v, float* __restrict__ out)
{
    int i4 = blockIdx.x * 1024 + threadIdx.x;   // 8192 blocks * 1024 = N/4
    int pos = i4 >> 4;                           // 16 float4 per position
    int bh  = pos >> 13;                         // / 8192
    float w = g_w[pos] * g_rsum[bh];
    float4 vv = ((const float4*)v)[i4];
    vv.x *= w; vv.y *= w; vv.z *= w; vv.w *= w;
    ((float4*)out)[i4] = vv;
}

extern "C" void kernel_launch(void* const* d_in, const int* in_sizes, int n_in,
                              void* d_out, int out_size)
{
    const float* q    = (const float*)d_in[0];
    const float* k    = (const float*)d_in[1];
    const float* v    = (const float*)d_in[2];
    const int*   mask = (const int*)d_in[3];
    const float* Wa_w = (const float*)d_in[4];
    const float* Wa_b = (const float*)d_in[5];
    const float* Ua_w = (const float*)d_in[6];
    const float* Ua_b = (const float*)d_in[7];
    const float* va_w = (const float*)d_in[8];
    const float* va_b = (const float*)d_in[9];
    float* out = (float*)d_out;

    attn_logits_kernel<<<NPOS / TS, 256>>>(q, k, mask, Wa_w, Wa_b,
                                           Ua_w, Ua_b, va_w, va_b);
    row_sum_kernel<<<BH, 256>>>();
    scale_v_kernel<<<(NPOS * DD / 4) / 1024, 1024>>>(v, out);
}

// round 10
// speedup vs baseline: 4.0572x; 1.5693x over previous
#include <cuda_runtime.h>
#include <cuda_bf16.h>
#include <cstdint>

// Problem constants
#define BB 4
#define HH 16
#define LL 8192
#define DD 64
#define BH (BB*HH)            // 64
#define NPOS (BH*LL)          // 524288

#define TS 128                // positions per block (M tile)
#define RSB 256               // bf16 row stride bytes (128 k-vals); XOR-swizzled

// Scratch (no cudaMalloc allowed)
__device__ float g_w[NPOS];
__device__ float g_rsum[BH];

__device__ __forceinline__ float tanh_fast(float x) {
    float xc = fminf(fmaxf(x, -15.f), 15.f);
    float z = __expf(2.f * xc);
    return __fdividef(z - 1.f, z + 1.f);
}

__device__ __forceinline__ uint32_t pack_bf16(float lo, float hi) {
    uint32_t r;
    asm("cvt.rn.bf16x2.f32 %0, %1, %2;" : "=r"(r) : "f"(hi), "f"(lo));
    return r;
}

#define LDSM_X4(r, addr) \
    asm volatile("ldmatrix.sync.aligned.m8n8.x4.shared.b16 {%0,%1,%2,%3}, [%4];" \
        : "=r"((r)[0]), "=r"((r)[1]), "=r"((r)[2]), "=r"((r)[3]) : "r"(addr))

#define MMA_BF16(c, a, b0_, b1_) \
    asm volatile( \
        "mma.sync.aligned.m16n8k16.row.col.f32.bf16.bf16.f32 " \
        "{%0,%1,%2,%3}, {%4,%5,%6,%7}, {%8,%9}, {%0,%1,%2,%3};" \
        : "+f"((c)[0]), "+f"((c)[1]), "+f"((c)[2]), "+f"((c)[3]) \
        : "r"((a)[0]), "r"((a)[1]), "r"((a)[2]), "r"((a)[3]), \
          "r"(b0_), "r"(b1_))

// ---------------------------------------------------------------------------
// Kernel 1: bf16 mma.sync GEMM [128 pos x 64 dims, K=128 single phase]
//   e = va . tanh(Wa q + Ua k + b);  w = mask ? exp(e) : 0
// 256 threads / 8 warps; warp-tile 16 pos x 64 dims.
// Staging: linear-copy (coalesced LDG) + XOR-swizzled smem (conflict-free
// STS.128 and ldmatrix). Row r, 16B-chunk c stored at r*256 + (c^(r&7))*16.
// ---------------------------------------------------------------------------
__global__ __launch_bounds__(256, 3) void attn_logits_kernel(
    const float* __restrict__ q, const float* __restrict__ k,
    const int* __restrict__ mask,
    const float* __restrict__ Wa_w, const float* __restrict__ Wa_b,
    const float* __restrict__ Ua_w, const float* __restrict__ Ua_b,
    const float* __restrict__ va_w, const float* __restrict__ va_b)
{
    __shared__ alignas(16) __nv_bfloat16 Xs[TS * 128];   // [128 pos][128 k] swz
    __shared__ alignas(16) __nv_bfloat16 Wsm[DD * 128];  // [64 n][128 k] swz
    __shared__ float bias[DD];
    __shared__ float vas[DD];

    const int t    = threadIdx.x;      // 0..255
    const int lane = t & 31;
    const int w    = t >> 5;           // 0..7
    const int gid  = lane >> 2;        // 0..7
    const int tig  = lane & 3;         // 0..3
    const int pos0 = blockIdx.x * TS;
    const int m0   = w * 16;           // warp's 16-pos row base

    const uint32_t sbX = (uint32_t)__cvta_generic_to_shared(Xs);
    const uint32_t sbW = (uint32_t)__cvta_generic_to_shared(Wsm);

    if (t < 64) {
        bias[t] = Wa_b[t] + Ua_b[t];
        vas[t]  = va_w[t];
    }

    // ---- stage X (q -> chunks 0..7, k -> chunks 8..15), linear copy ----
    // idx8 in [0,1024): pos = idx8>>3, c = idx8&7 (32B fp32 -> 16B bf16 chunk)
    #pragma unroll
    for (int it = 0; it < 4; it++) {
        const int idx8 = t + it * 256;
        const int pos = idx8 >> 3, c = idx8 & 7;
        const float4* s4 = (const float4*)(q + (size_t)(pos0 + pos) * DD) + 2 * c;
        float4 a = s4[0], b = s4[1];
        uint4 u;
        u.x = pack_bf16(a.x, a.y); u.y = pack_bf16(a.z, a.w);
        u.z = pack_bf16(b.x, b.y); u.w = pack_bf16(b.z, b.w);
        const int ch = c ^ (pos & 7);
        *(uint4*)((char*)Xs + pos * RSB + ch * 16) = u;
    }
    #pragma unroll
    for (int it = 0; it < 4; it++) {
        const int idx8 = t + it * 256;
        const int pos = idx8 >> 3, c = idx8 & 7;
        const float4* s4 = (const float4*)(k + (size_t)(pos0 + pos) * DD) + 2 * c;
        float4 a = s4[0], b = s4[1];
        uint4 u;
        u.x = pack_bf16(a.x, a.y); u.y = pack_bf16(a.z, a.w);
        u.z = pack_bf16(b.x, b.y); u.w = pack_bf16(b.z, b.w);
        const int ch = (8 + c) ^ (pos & 7);
        *(uint4*)((char*)Xs + pos * RSB + ch * 16) = u;
    }
    // ---- stage W (Wa -> chunks 0..7, Ua -> 8..15) ----
    #pragma unroll
    for (int it = 0; it < 2; it++) {
        const int idx8 = t + it * 256;
        const int pos = idx8 >> 3, c = idx8 & 7;
        const float4* s4 = (const float4*)(Wa_w + (size_t)pos * DD) + 2 * c;
        float4 a = s4[0], b = s4[1];
        uint4 u;
        u.x = pack_bf16(a.x, a.y); u.y = pack_bf16(a.z, a.w);
        u.z = pack_bf16(b.x, b.y); u.w = pack_bf16(b.z, b.w);
        const int ch = c ^ (pos & 7);
        *(uint4*)((char*)Wsm + pos * RSB + ch * 16) = u;
    }
    #pragma unroll
    for (int it = 0; it < 2; it++) {
        const int idx8 = t + it * 256;
        const int pos = idx8 >> 3, c = idx8 & 7;
        const float4* s4 = (const float4*)(Ua_w + (size_t)pos * DD) + 2 * c;
        float4 a = s4[0], b = s4[1];
        uint4 u;
        u.x = pack_bf16(a.x, a.y); u.y = pack_bf16(a.z, a.w);
        u.z = pack_bf16(b.x, b.y); u.w = pack_bf16(b.z, b.w);
        const int ch = (8 + c) ^ (pos & 7);
        *(uint4*)((char*)Wsm + pos * RSB + ch * 16) = u;
    }
    __syncthreads();

    float acc[8][4];
    #pragma unroll
    for (int nt = 0; nt < 8; nt++)
        #pragma unroll
        for (int j = 0; j < 4; j++) acc[nt][j] = 0.f;

    // ldmatrix lane bases (swizzle applied per k-step)
    const int rowA = m0 + (lane & 15);
    const uint32_t baseA = sbX + (uint32_t)rowA * RSB;
    const int swA = rowA & 7;
    const int ckA0 = lane >> 4;                    // 0/1
    const int rowB = ((lane >> 4) << 3) + (lane & 7);
    const uint32_t baseB = sbW + (uint32_t)rowB * RSB;
    const int swB = rowB & 7;
    const int ckB0 = (lane >> 3) & 1;              // 0/1

    #pragma unroll
    for (int ks = 0; ks < 8; ks++) {               // K=128, k16 per MMA
        uint32_t af[4];
        LDSM_X4(af, baseA + (uint32_t)(((2 * ks + ckA0) ^ swA) << 4));
        uint32_t bf[4][4];
        #pragma unroll
        for (int np = 0; np < 4; np++)
            LDSM_X4(bf[np], baseB + (uint32_t)(np * 16 * RSB)
                          + (uint32_t)(((2 * ks + ckB0) ^ ((rowB + np * 16) & 7)) << 4));
        #pragma unroll
        for (int np = 0; np < 4; np++) {
            MMA_BF16(acc[2 * np],     af, bf[np][0], bf[np][1]);
            MMA_BF16(acc[2 * np + 1], af, bf[np][2], bf[np][3]);
        }
    }

    // ---- epilogue: tanh, va-dot, 4-lane reduce, masked exp ----
    const float vb = va_b[0];
    float s0 = 0.f, s1 = 0.f;
    #pragma unroll
    for (int nt = 0; nt < 8; nt++) {
        const int c0 = nt * 8 + 2 * tig;
        const float vv0 = vas[c0], vv1 = vas[c0 + 1];
        const float bb0 = bias[c0], bb1 = bias[c0 + 1];
        s0 += vv0 * tanh_fast(acc[nt][0] + bb0)
            + vv1 * tanh_fast(acc[nt][1] + bb1);
        s1 += vv0 * tanh_fast(acc[nt][2] + bb0)
            + vv1 * tanh_fast(acc[nt][3] + bb1);
    }
    s0 += __shfl_xor_sync(0xffffffffu, s0, 1, 4);
    s0 += __shfl_xor_sync(0xffffffffu, s0, 2, 4);
    s1 += __shfl_xor_sync(0xffffffffu, s1, 1, 4);
    s1 += __shfl_xor_sync(0xffffffffu, s1, 2, 4);
    if (tig == 0) {
        int p0 = pos0 + m0 + gid;
        float e0 = s0 + vb;
        g_w[p0] = (mask[p0] != 0) ? __expf(e0) : 0.f;
        int p1 = p0 + 8;
        float e1 = s1 + vb;
        g_w[p1] = (mask[p1] != 0) ? __expf(e1) : 0.f;
    }
}

// ---------------------------------------------------------------------------
// Kernel 2: per-(b,h) sum of w over L, store reciprocal. Deterministic.
// ---------------------------------------------------------------------------
__global__ __launch_bounds__(256) void row_sum_kernel()
{
    __shared__ float red[256];
    int bh = blockIdx.x;
    int t = threadIdx.x;
    float s = 0.f;
    const float4* wrow = (const float4*)(g_w + (size_t)bh * LL);
    for (int l = t; l < LL / 4; l += 256) {
        float4 w4 = wrow[l];
        s += (w4.x + w4.y) + (w4.z + w4.w);
    }
    red[t] = s;
    __syncthreads();
    for (int m = 128; m > 0; m >>= 1) {
        if (t < m) red[t] += red[t + m];
        __syncthreads();
    }
    if (t == 0) g_rsum[bh] = 1.f / red[0];
}

// ---------------------------------------------------------------------------
// Kernel 3: out = alpha * v  (float4)
// ---------------------------------------------------------------------------
__global__ __launch_bounds__(1024) void scale_v_kernel(
    const float* __restrict__ v, float* __restrict__ out)
{
    int i4 = blockIdx.x * 1024 + threadIdx.x;   // 8192 blocks * 1024 = N/4
    int pos = i4 >> 4;                           // 16 float4 per position
    int bh  = pos >> 13;                         // / 8192
    float w = g_w[pos] * g_rsum[bh];
    float4 vv = ((const float4*)v)[i4];
    vv.x *= w; vv.y *= w; vv.z *= w; vv.w *= w;
    ((float4*)out)[i4] = vv;
}

extern "C" void kernel_launch(void* const* d_in, const int* in_sizes, int n_in,
                              void* d_out, int out_size)
{
    const float* q    = (const float*)d_in[0];
    const float* k    = (const float*)d_in[1];
    const float* v    = (const float*)d_in[2];
    const int*   mask = (const int*)d_in[3];
    const float* Wa_w = (const float*)d_in[4];
    const float* Wa_b = (const float*)d_in[5];
    const float* Ua_w = (const float*)d_in[6];
    const float* Ua_b = (const float*)d_in[7];
    const float* va_w = (const float*)d_in[8];
    const float* va_b = (const float*)d_in[9];
    float* out = (float*)d_out;

    attn_logits_kernel<<<NPOS / TS, 256>>>(q, k, mask, Wa_w, Wa_b,
                                           Ua_w, Ua_b, va_w, va_b);
    row_sum_kernel<<<BH, 256>>>();
    scale_v_kernel<<<(NPOS * DD / 4) / 1024, 1024>>>(v, out);
}

// round 11
// speedup vs baseline: 4.1202x; 1.0155x over previous
#include <cuda_runtime.h>
#include <cuda_bf16.h>
#include <cstdint>

// Problem constants
#define BB 4
#define HH 16
#define LL 8192
#define DD 64
#define BH (BB*HH)            // 64
#define NPOS (BH*LL)          // 524288

#define TS 256                // positions per block (M tile)
#define RSB 256               // bf16 row stride bytes (128 k-vals); XOR-swizzled

// Scratch (no cudaMalloc allowed)
__device__ float g_w[NPOS];
__device__ float g_rsum[BH];

__device__ __forceinline__ float tanh_fast(float x) {
    float xc = fminf(fmaxf(x, -15.f), 15.f);
    float z = __expf(2.f * xc);
    return __fdividef(z - 1.f, z + 1.f);
}

__device__ __forceinline__ uint32_t pack_bf16(float lo, float hi) {
    uint32_t r;
    asm("cvt.rn.bf16x2.f32 %0, %1, %2;" : "=r"(r) : "f"(hi), "f"(lo));
    return r;
}

#define LDSM_X4(r, addr) \
    asm volatile("ldmatrix.sync.aligned.m8n8.x4.shared.b16 {%0,%1,%2,%3}, [%4];" \
        : "=r"((r)[0]), "=r"((r)[1]), "=r"((r)[2]), "=r"((r)[3]) : "r"(addr))

#define MMA_BF16(c, a, b0_, b1_) \
    asm volatile( \
        "mma.sync.aligned.m16n8k16.row.col.f32.bf16.bf16.f32 " \
        "{%0,%1,%2,%3}, {%4,%5,%6,%7}, {%8,%9}, {%0,%1,%2,%3};" \
        : "+f"((c)[0]), "+f"((c)[1]), "+f"((c)[2]), "+f"((c)[3]) \
        : "r"((a)[0]), "r"((a)[1]), "r"((a)[2]), "r"((a)[3]), \
          "r"(b0_), "r"(b1_))

// ---------------------------------------------------------------------------
// Kernel 1: bf16 mma.sync GEMM [256 pos x 64 dims, K=128 single phase]
//   e = va . tanh(Wa q + Ua k + b);  w = mask ? exp(e) : 0
// 256 threads / 8 warps; warp-tile 32 pos x 64 dims (2 m-tiles) to amortize
// the per-warp B-fragment LDSM duplication. XOR-swizzled smem, coalesced LDG.
// ---------------------------------------------------------------------------
__global__ __launch_bounds__(256, 2) void attn_logits_kernel(
    const float* __restrict__ q, const float* __restrict__ k,
    const int* __restrict__ mask,
    const float* __restrict__ Wa_w, const float* __restrict__ Wa_b,
    const float* __restrict__ Ua_w, const float* __restrict__ Ua_b,
    const float* __restrict__ va_w, const float* __restrict__ va_b)
{
    __shared__ alignas(16) __nv_bfloat16 Xs[TS * 128];   // [256 pos][128 k] swz
    __shared__ alignas(16) __nv_bfloat16 Wsm[DD * 128];  // [64 n][128 k] swz
    __shared__ float bias[DD];
    __shared__ float vas[DD];

    const int t    = threadIdx.x;      // 0..255
    const int lane = t & 31;
    const int w    = t >> 5;           // 0..7
    const int gid  = lane >> 2;        // 0..7
    const int tig  = lane & 3;         // 0..3
    const int pos0 = blockIdx.x * TS;
    const int m0   = w * 32;           // warp's 32-pos row base

    const uint32_t sbX = (uint32_t)__cvta_generic_to_shared(Xs);
    const uint32_t sbW = (uint32_t)__cvta_generic_to_shared(Wsm);

    if (t < 64) {
        bias[t] = Wa_b[t] + Ua_b[t];
        vas[t]  = va_w[t];
    }

    // ---- stage X (q -> chunks 0..7, k -> chunks 8..15), linear copy ----
    #pragma unroll
    for (int it = 0; it < 8; it++) {
        const int idx8 = t + it * 256;            // 0..2047
        const int pos = idx8 >> 3, c = idx8 & 7;
        const float4* s4 = (const float4*)(q + (size_t)(pos0 + pos) * DD) + 2 * c;
        float4 a = s4[0], b = s4[1];
        uint4 u;
        u.x = pack_bf16(a.x, a.y); u.y = pack_bf16(a.z, a.w);
        u.z = pack_bf16(b.x, b.y); u.w = pack_bf16(b.z, b.w);
        const int ch = c ^ (pos & 7);
        *(uint4*)((char*)Xs + pos * RSB + ch * 16) = u;
    }
    #pragma unroll
    for (int it = 0; it < 8; it++) {
        const int idx8 = t + it * 256;
        const int pos = idx8 >> 3, c = idx8 & 7;
        const float4* s4 = (const float4*)(k + (size_t)(pos0 + pos) * DD) + 2 * c;
        float4 a = s4[0], b = s4[1];
        uint4 u;
        u.x = pack_bf16(a.x, a.y); u.y = pack_bf16(a.z, a.w);
        u.z = pack_bf16(b.x, b.y); u.w = pack_bf16(b.z, b.w);
        const int ch = (8 + c) ^ (pos & 7);
        *(uint4*)((char*)Xs + pos * RSB + ch * 16) = u;
    }
    // ---- stage W (Wa -> chunks 0..7, Ua -> 8..15) ----
    #pragma unroll
    for (int it = 0; it < 2; it++) {
        const int idx8 = t + it * 256;            // 0..511
        const int pos = idx8 >> 3, c = idx8 & 7;
        const float4* s4 = (const float4*)(Wa_w + (size_t)pos * DD) + 2 * c;
        float4 a = s4[0], b = s4[1];
        uint4 u;
        u.x = pack_bf16(a.x, a.y); u.y = pack_bf16(a.z, a.w);
        u.z = pack_bf16(b.x, b.y); u.w = pack_bf16(b.z, b.w);
        const int ch = c ^ (pos & 7);
        *(uint4*)((char*)Wsm + pos * RSB + ch * 16) = u;
    }
    #pragma unroll
    for (int it = 0; it < 2; it++) {
        const int idx8 = t + it * 256;
        const int pos = idx8 >> 3, c = idx8 & 7;
        const float4* s4 = (const float4*)(Ua_w + (size_t)pos * DD) + 2 * c;
        float4 a = s4[0], b = s4[1];
        uint4 u;
        u.x = pack_bf16(a.x, a.y); u.y = pack_bf16(a.z, a.w);
        u.z = pack_bf16(b.x, b.y); u.w = pack_bf16(b.z, b.w);
        const int ch = (8 + c) ^ (pos & 7);
        *(uint4*)((char*)Wsm + pos * RSB + ch * 16) = u;
    }
    __syncthreads();

    float acc[2][8][4];
    #pragma unroll
    for (int mt = 0; mt < 2; mt++)
        #pragma unroll
        for (int nt = 0; nt < 8; nt++)
            #pragma unroll
            for (int j = 0; j < 4; j++) acc[mt][nt][j] = 0.f;

    // ldmatrix lane bases (swizzle applied per k-step)
    const int rowA = m0 + (lane & 15);
    const uint32_t baseA = sbX + (uint32_t)rowA * RSB;
    const int swA = rowA & 7;
    const int ckA0 = lane >> 4;                    // 0/1
    const int rowB = ((lane >> 4) << 3) + (lane & 7);
    const uint32_t baseB = sbW + (uint32_t)rowB * RSB;
    const int ckB0 = (lane >> 3) & 1;              // 0/1

    #pragma unroll
    for (int ks = 0; ks < 8; ks++) {               // K=128, k16 per MMA
        uint32_t af[2][4];
        LDSM_X4(af[0], baseA + (uint32_t)(((2 * ks + ckA0) ^ swA) << 4));
        LDSM_X4(af[1], baseA + 16u * RSB
                     + (uint32_t)(((2 * ks + ckA0) ^ ((rowA + 16) & 7)) << 4));
        uint32_t bf[4][4];
        #pragma unroll
        for (int np = 0; np < 4; np++)
            LDSM_X4(bf[np], baseB + (uint32_t)(np * 16 * RSB)
                          + (uint32_t)(((2 * ks + ckB0) ^ ((rowB + np * 16) & 7)) << 4));
        #pragma unroll
        for (int mt = 0; mt < 2; mt++)
            #pragma unroll
            for (int np = 0; np < 4; np++) {
                MMA_BF16(acc[mt][2 * np],     af[mt], bf[np][0], bf[np][1]);
                MMA_BF16(acc[mt][2 * np + 1], af[mt], bf[np][2], bf[np][3]);
            }
    }

    // ---- epilogue: tanh, va-dot, 4-lane reduce, masked exp ----
    const float vb = va_b[0];
    #pragma unroll
    for (int mt = 0; mt < 2; mt++) {
        float s0 = 0.f, s1 = 0.f;
        #pragma unroll
        for (int nt = 0; nt < 8; nt++) {
            const int c0 = nt * 8 + 2 * tig;
            const float vv0 = vas[c0], vv1 = vas[c0 + 1];
            const float bb0 = bias[c0], bb1 = bias[c0 + 1];
            s0 += vv0 * tanh_fast(acc[mt][nt][0] + bb0)
                + vv1 * tanh_fast(acc[mt][nt][1] + bb1);
            s1 += vv0 * tanh_fast(acc[mt][nt][2] + bb0)
                + vv1 * tanh_fast(acc[mt][nt][3] + bb1);
        }
        s0 += __shfl_xor_sync(0xffffffffu, s0, 1, 4);
        s0 += __shfl_xor_sync(0xffffffffu, s0, 2, 4);
        s1 += __shfl_xor_sync(0xffffffffu, s1, 1, 4);
        s1 += __shfl_xor_sync(0xffffffffu, s1, 2, 4);
        if (tig == 0) {
            int p0 = pos0 + m0 + mt * 16 + gid;
            float e0 = s0 + vb;
            g_w[p0] = (mask[p0] != 0) ? __expf(e0) : 0.f;
            int p1 = p0 + 8;
            float e1 = s1 + vb;
            g_w[p1] = (mask[p1] != 0) ? __expf(e1) : 0.f;
        }
    }
}

// ---------------------------------------------------------------------------
// Kernel 2: per-(b,h) sum of w over L, store reciprocal. Deterministic.
// ---------------------------------------------------------------------------
__global__ __launch_bounds__(256) void row_sum_kernel()
{
    __shared__ float red[256];
    int bh = blockIdx.x;
    int t = threadIdx.x;
    float s = 0.f;
    const float4* wrow = (const float4*)(g_w + (size_t)bh * LL);
    for (int l = t; l < LL / 4; l += 256) {
        float4 w4 = wrow[l];
        s += (w4.x + w4.y) + (w4.z + w4.w);
    }
    red[t] = s;
    __syncthreads();
    for (int m = 128; m > 0; m >>= 1) {
        if (t < m) red[t] += red[t + m];
        __syncthreads();
    }
    if (t == 0) g_rsum[bh] = 1.f / red[0];
}

// ---------------------------------------------------------------------------
// Kernel 3: out = alpha * v  (float4)
// ---------------------------------------------------------------------------
__global__ __launch_bounds__(1024) void scale_v_kernel(
    const float* __restrict__ v, float* __restrict__ out)
{
    int i4 = blockIdx.x * 1024 + threadIdx.x;   // 8192 blocks * 1024 = N/4
    int pos = i4 >> 4;                           // 16 float4 per position
    int bh  = pos >> 13;                         // / 8192
    float w = g_w[pos] * g_rsum[bh];
    float4 vv = ((const float4*)v)[i4];
    vv.x *= w; vv.y *= w; vv.z *= w; vv.w *= w;
    ((float4*)out)[i4] = vv;
}

extern "C" void kernel_launch(void* const* d_in, const int* in_sizes, int n_in,
                              void* d_out, int out_size)
{
    const float* q    = (const float*)d_in[0];
    const float* k    = (const float*)d_in[1];
    const float* v    = (const float*)d_in[2];
    const int*   mask = (const int*)d_in[3];
    const float* Wa_w = (const float*)d_in[4];
    const float* Wa_b = (const float*)d_in[5];
    const float* Ua_w = (const float*)d_in[6];
    const float* Ua_b = (const float*)d_in[7];
    const float* va_w = (const float*)d_in[8];
    const float* va_b = (const float*)d_in[9];
    float* out = (float*)d_out;

    attn_logits_kernel<<<NPOS / TS, 256>>>(q, k, mask, Wa_w, Wa_b,
                                           Ua_w, Ua_b, va_w, va_b);
    row_sum_kernel<<<BH, 256>>>();
    scale_v_kernel<<<(NPOS * DD / 4) / 1024, 1024>>>(v, out);
}